// round 16
// baseline (speedup 1.0000x reference)
#include <cuda_runtime.h>
#include <cuda_bf16.h>
#include <cstdint>

#define N_NODES 50000
#define N_EDGES 800000
#define D       128
#define T_REL   8
#define PAD     136   // bf16 elems per smem row (272B = 17 x 16B chunks)
#define NKEYS   (N_NODES * T_REL)        // 400000
#define SCAN_B  512
#define NBLK    ((NKEYS + SCAN_B - 1) / SCAN_B)   // 782

// ---------------- scratch (static device globals; no allocation) ----------------
__device__ float g_Ht  [(size_t)N_NODES * T_REL * D];   // 204.8 MB, layout [t][n][f] == [key][f]
__device__ float g_aggr[(size_t)N_NODES * D];           //  25.6 MB
__device__ float g_gh  [(size_t)N_NODES * 3 * D];       //  76.8 MB

__device__ __nv_bfloat16 g_h_hi[(size_t)N_NODES * D];   // pre-split h
__device__ __nv_bfloat16 g_h_lo[(size_t)N_NODES * D];

// B fragments: per tile 4 wn x 8 ks x 2 p x 32 lanes = 2048 uint4 (32 KB)
__device__ uint4 g_wrelF_hi[T_REL * 2048];
__device__ uint4 g_wrelF_lo[T_REL * 2048];
__device__ uint4 g_wihF_hi[3 * 2048];
__device__ uint4 g_wihF_lo[3 * 2048];
__device__ uint4 g_whhF_hi[3 * 2048];
__device__ uint4 g_whhF_lo[3 * 2048];

// edge sort scratch (type-major keys: key = type*N + src)
__device__ int g_hist[NKEYS];
__device__ int g_off [NKEYS];    // after reorder: END offset per key (CSR)
__device__ int g_bsum[1024];
__device__ int g_sdst[N_EDGES];

// ---------------- helpers ----------------
__device__ __forceinline__ uint32_t smem_u32(const void* p) {
    uint32_t a;
    asm("{ .reg .u64 t; cvta.to.shared.u64 t, %1; cvt.u32.u64 %0, t; }" : "=r"(a) : "l"(p));
    return a;
}
__device__ __forceinline__ void split2(float v, __nv_bfloat16& hi, __nv_bfloat16& lo) {
    hi = __float2bfloat16(v);
    lo = __float2bfloat16(v - __bfloat162float(hi));
}
__device__ __forceinline__ void ldsm_x4(uint32_t* r, uint32_t addr) {
    asm volatile("ldmatrix.sync.aligned.m8n8.x4.shared.b16 {%0,%1,%2,%3}, [%4];"
                 : "=r"(r[0]), "=r"(r[1]), "=r"(r[2]), "=r"(r[3]) : "r"(addr));
}
__device__ __forceinline__ void mma_bf16(float* c, const uint32_t* a, uint32_t b0, uint32_t b1) {
    asm volatile("mma.sync.aligned.m16n8k16.row.col.f32.bf16.bf16.f32 "
                 "{%0,%1,%2,%3}, {%4,%5,%6,%7}, {%8,%9}, {%0,%1,%2,%3};"
                 : "+f"(c[0]), "+f"(c[1]), "+f"(c[2]), "+f"(c[3])
                 : "r"(a[0]), "r"(a[1]), "r"(a[2]), "r"(a[3]), "r"(b0), "r"(b1));
}
__device__ __forceinline__ float sigmoidf_(float v) { return 1.f / (1.f + expf(-v)); }

// ---------------- small kernels ----------------
__global__ void embed_kernel(const int* __restrict__ x, const float* __restrict__ emb,
                             float* __restrict__ h)
{
    int g = blockIdx.x * blockDim.x + threadIdx.x;
    if (g >= N_NODES * (D / 4)) return;
    int n = g >> 5, c = g & 31;
    float4 v = ((const float4*)emb)[(size_t)x[n] * 32 + c];
    ((float4*)h)[n * 32 + c] = v;
    size_t base = (size_t)n * D + c * 4;
    __nv_bfloat16 hx, lx, hy, ly, hz, lz, hw, lw;
    split2(v.x, hx, lx); split2(v.y, hy, ly);
    split2(v.z, hz, lz); split2(v.w, hw, lw);
    *(__nv_bfloat162*)(g_h_hi + base)     = __nv_bfloat162(hx, hy);
    *(__nv_bfloat162*)(g_h_hi + base + 2) = __nv_bfloat162(hz, hw);
    *(__nv_bfloat162*)(g_h_lo + base)     = __nv_bfloat162(lx, ly);
    *(__nv_bfloat162*)(g_h_lo + base + 2) = __nv_bfloat162(lz, lw);
}

__global__ void init_aggr_kernel(const int* __restrict__ node_type,
                                 const float* __restrict__ b_node)
{
    int g = blockIdx.x * blockDim.x + threadIdx.x;
    if (g >= N_NODES * (D / 4)) return;
    int n = g >> 5, c = g & 31;
    ((float4*)g_aggr)[n * 32 + c] = ((const float4*)b_node)[(size_t)node_type[n] * 32 + c];
}

// ---------------- edge counting sort, type-major (once per launch) ----------------
__global__ void zero_hist_kernel()
{
    int i = blockIdx.x * blockDim.x + threadIdx.x;
    if (i < NKEYS) g_hist[i] = 0;
}

__global__ void hist_kernel(const int* __restrict__ edge_index,
                            const int* __restrict__ edge_type)
{
    int e = blockIdx.x * blockDim.x + threadIdx.x;
    if (e >= N_EDGES) return;
    int key = edge_type[e] * N_NODES + edge_index[e];
    atomicAdd(&g_hist[key], 1);
}

__global__ void scan1_kernel()
{
    __shared__ int s[SCAN_B];
    int b = blockIdx.x, t = threadIdx.x, i = b * SCAN_B + t;
    int v = (i < NKEYS) ? g_hist[i] : 0;
    s[t] = v;
    __syncthreads();
#pragma unroll
    for (int o = 1; o < SCAN_B; o <<= 1) {
        int x = (t >= o) ? s[t - o] : 0;
        __syncthreads();
        if (t >= o) s[t] += x;
        __syncthreads();
    }
    if (i < NKEYS) g_off[i] = s[t] - v;
    if (t == SCAN_B - 1) g_bsum[b] = s[t];
}

__global__ void scan2_kernel()
{
    __shared__ int s[1024];
    int t = threadIdx.x;
    int v = (t < NBLK) ? g_bsum[t] : 0;
    s[t] = v;
    __syncthreads();
#pragma unroll
    for (int o = 1; o < 1024; o <<= 1) {
        int x = (t >= o) ? s[t - o] : 0;
        __syncthreads();
        if (t >= o) s[t] += x;
        __syncthreads();
    }
    if (t < NBLK) g_bsum[t] = s[t] - v;
}

__global__ void scan3_kernel()
{
    int b = blockIdx.x, i = b * SCAN_B + threadIdx.x;
    if (i < NKEYS) g_off[i] += g_bsum[b];
}

__global__ void reorder_kernel(const int* __restrict__ edge_index,
                               const int* __restrict__ edge_type)
{
    int e = blockIdx.x * blockDim.x + threadIdx.x;
    if (e >= N_EDGES) return;
    int key = edge_type[e] * N_NODES + edge_index[e];
    int pos = atomicAdd(&g_off[key], 1);   // leaves g_off[key] = END offset
    g_sdst[pos] = edge_index[N_EDGES + e];
}

// ---------------- CSR scatter for nT types starting at tBase: warp per key ----------------
__global__ void scatter_csr_kernel(int tBase, int nT)
{
    int gw = (blockIdx.x * blockDim.x + threadIdx.x) >> 5;   // key within chunk
    int lane = threadIdx.x & 31;
    if (gw >= nT * N_NODES) return;
    int key = tBase * N_NODES + gw;
    int start = (key == 0) ? 0 : __ldg(g_off + key - 1);
    int end   = __ldg(g_off + key);
    if (start == end) return;
    float4 v = __ldg(((const float4*)g_Ht) + (size_t)key * 32 + lane);
    for (int e = start; e < end; e++) {
        int dst = __ldg(g_sdst + e);
        float* p = g_aggr + (size_t)dst * D + lane * 4;
        asm volatile("red.global.add.v4.f32 [%0], {%1, %2, %3, %4};"
                     :: "l"(p), "f"(v.x), "f"(v.y), "f"(v.z), "f"(v.w) : "memory");
    }
}

// ---------------- unified weight prep: fp32 -> split -> fragments, ONE launch ----------------
// grid = 14 blocks: 0..7 = W_rel tiles (transposed), 8..10 = W_ih, 11..13 = W_hh.
#define SM_BYTES (2 * 128 * PAD * 2)

__global__ void weight_prep_kernel(const float* __restrict__ W_rel,
                                   const float* __restrict__ W_ih,
                                   const float* __restrict__ W_hh)
{
    extern __shared__ __nv_bfloat16 smem[];
    __nv_bfloat16* sBh = smem;
    __nv_bfloat16* sBl = smem + 128 * PAD;

    const int bT = blockIdx.x;
    const int tid = threadIdx.x, lane = tid & 31, w = tid >> 5;

    const float* src;
    uint4 *dstH, *dstL;
    bool trans;
    if (bT < 8) {
        src = W_rel + (size_t)bT * 128 * 128;
        dstH = g_wrelF_hi + (size_t)bT * 2048;
        dstL = g_wrelF_lo + (size_t)bT * 2048;
        trans = true;
    } else if (bT < 11) {
        int g = bT - 8;
        src = W_ih + (size_t)g * 128 * 128;
        dstH = g_wihF_hi + (size_t)g * 2048;
        dstL = g_wihF_lo + (size_t)g * 2048;
        trans = false;
    } else {
        int g = bT - 11;
        src = W_hh + (size_t)g * 128 * 128;
        dstH = g_whhF_hi + (size_t)g * 2048;
        dstL = g_whhF_lo + (size_t)g * 2048;
        trans = false;
    }

    for (int i = tid; i < 128 * 128; i += 256) {
        float v = src[i];
        int row, col;
        if (trans) { row = i & 127; col = i >> 7; }
        else       { row = i >> 7; col = i & 127; }
        __nv_bfloat16 hi, lo;
        split2(v, hi, lo);
        sBh[row * PAD + col] = hi;
        sBl[row * PAD + col] = lo;
    }
    __syncthreads();

    const uint32_t uBh = smem_u32(sBh), uBl = smem_u32(sBl);
    const int wn = w >> 1;
    for (int ksi = 0; ksi < 4; ksi++) {
        int ks = (w & 1) * 4 + ksi;
#pragma unroll
        for (int p = 0; p < 2; p++) {
            int row = wn * 32 + p * 16 + (lane & 7) + ((lane >> 4) << 3);
            uint32_t off = (uint32_t)(row * PAD + ((lane >> 3) & 1) * 8) * 2 + ks * 32;
            uint32_t r[4];
            ldsm_x4(r, uBh + off);
            dstH[((size_t)wn * 16 + ks * 2 + p) * 32 + lane] = make_uint4(r[0], r[1], r[2], r[3]);
            ldsm_x4(r, uBl + off);
            dstL[((size_t)wn * 16 + ks * 2 + p) * 32 + lane] = make_uint4(r[0], r[1], r[2], r[3]);
        }
    }
}

// ---------------- bf16x3 GEMM (Ht / gh): A pre-split bf16, 128x128 tile ----------------
__global__ __launch_bounds__(256, 2)
void gemm_mma_kernel(const __nv_bfloat16* __restrict__ Ahi,
                     const __nv_bfloat16* __restrict__ Alo,
                     const uint4* __restrict__ BfH,
                     const uint4* __restrict__ BfL,
                     float* __restrict__ C,
                     const float* __restrict__ bias,
                     int M, int ldc, size_t cBlockStride)
{
    extern __shared__ __nv_bfloat16 smem[];
    __nv_bfloat16* sAh = smem;
    __nv_bfloat16* sAl = smem + 128 * PAD;

    const int tid  = threadIdx.x;
    const int lane = tid & 31;
    const int wid  = tid >> 5;
    const int warp_m = wid & 1;
    const int warp_n = wid >> 1;
    const int m0 = blockIdx.x * 128;
    const int bT = blockIdx.y;

    {
        const uint4 zero = make_uint4(0, 0, 0, 0);
        for (int i = tid; i < 128 * 16; i += 256) {
            int r = i >> 4, c8 = i & 15;
            uint4 vh = zero, vl = zero;
            if (m0 + r < M) {
                vh = *(const uint4*)(Ahi + (size_t)(m0 + r) * 128 + c8 * 8);
                vl = *(const uint4*)(Alo + (size_t)(m0 + r) * 128 + c8 * 8);
            }
            int base = r * PAD + c8 * 8;
            *(uint4*)(sAh + base) = vh;
            *(uint4*)(sAl + base) = vl;
        }
    }
    __syncthreads();

    const uint32_t uAh = smem_u32(sAh), uAl = smem_u32(sAl);
    uint32_t offA[4];
#pragma unroll
    for (int mt = 0; mt < 4; mt++) {
        int row = warp_m * 64 + mt * 16 + (lane & 15);
        offA[mt] = (uint32_t)(row * PAD + (lane >> 4) * 8) * 2;
    }

    const uint4* bfh = BfH + ((size_t)bT * 4 + warp_n) * 16 * 32 + lane;
    const uint4* bfl = BfL + ((size_t)bT * 4 + warp_n) * 16 * 32 + lane;

    float acc[4][4][4];
#pragma unroll
    for (int a = 0; a < 4; a++)
#pragma unroll
        for (int b = 0; b < 4; b++)
#pragma unroll
            for (int c = 0; c < 4; c++) acc[a][b][c] = 0.f;

    uint4 ph0 = __ldg(bfh + 0 * 32), ph1 = __ldg(bfh + 1 * 32);
    uint4 pl0 = __ldg(bfl + 0 * 32), pl1 = __ldg(bfl + 1 * 32);

#pragma unroll
    for (int ks = 0; ks < 8; ks++) {
        const uint32_t kb = ks * 32;
        uint32_t bh[2][4] = {{ph0.x, ph0.y, ph0.z, ph0.w}, {ph1.x, ph1.y, ph1.z, ph1.w}};
        uint32_t bl[2][4] = {{pl0.x, pl0.y, pl0.z, pl0.w}, {pl1.x, pl1.y, pl1.z, pl1.w}};
        if (ks < 7) {
            ph0 = __ldg(bfh + ((ks + 1) * 2 + 0) * 32);
            ph1 = __ldg(bfh + ((ks + 1) * 2 + 1) * 32);
            pl0 = __ldg(bfl + ((ks + 1) * 2 + 0) * 32);
            pl1 = __ldg(bfl + ((ks + 1) * 2 + 1) * 32);
        }
#pragma unroll
        for (int mt = 0; mt < 4; mt++) {
            uint32_t ah[4], al[4];
            ldsm_x4(ah, uAh + offA[mt] + kb);
            ldsm_x4(al, uAl + offA[mt] + kb);
#pragma unroll
            for (int nt = 0; nt < 4; nt++) {
                const int p = nt >> 1, s = (nt & 1) * 2;
                mma_bf16(acc[mt][nt], ah, bh[p][s], bh[p][s + 1]);
            }
#pragma unroll
            for (int nt = 0; nt < 4; nt++) {
                const int p = nt >> 1, s = (nt & 1) * 2;
                mma_bf16(acc[mt][nt], al, bh[p][s], bh[p][s + 1]);
            }
#pragma unroll
            for (int nt = 0; nt < 4; nt++) {
                const int p = nt >> 1, s = (nt & 1) * 2;
                mma_bf16(acc[mt][nt], ah, bl[p][s], bl[p][s + 1]);
            }
        }
    }

    float* Cb = C + (size_t)bT * cBlockStride;
#pragma unroll
    for (int mt = 0; mt < 4; mt++) {
        int row0 = m0 + warp_m * 64 + mt * 16 + (lane >> 2);
#pragma unroll
        for (int nt = 0; nt < 4; nt++) {
            int col = warp_n * 32 + nt * 8 + (lane & 3) * 2;
            float b0 = 0.f, b1 = 0.f;
            if (bias) { b0 = bias[bT * 128 + col]; b1 = bias[bT * 128 + col + 1]; }
            if (row0 < M) {
                float2 v = make_float2(acc[mt][nt][0] + b0, acc[mt][nt][1] + b1);
                *(float2*)(Cb + (size_t)row0 * ldc + col) = v;
            }
            if (row0 + 8 < M) {
                float2 v = make_float2(acc[mt][nt][2] + b0, acc[mt][nt][3] + b1);
                *(float2*)(Cb + (size_t)(row0 + 8) * ldc + col) = v;
            }
        }
    }
}

// ---------------- fused gi GEMM + GRU gates (also emits split h) ----------------
#define SMF_BYTES (2 * 32 * PAD * 2)

__global__ __launch_bounds__(256, 2)
void gru_fused_kernel(const float* __restrict__ A,          // aggr [M,128] (fp32, split here)
                      const uint4* __restrict__ BfH,        // wihF hi (3 tiles)
                      const uint4* __restrict__ BfL,
                      const float* __restrict__ gh,         // [M, 384] (b_hh added)
                      const float* __restrict__ b_ih,       // [384]
                      float* __restrict__ h,                // [M, 128] in/out
                      int M)
{
    extern __shared__ __nv_bfloat16 smem[];
    __nv_bfloat16* sAh = smem;
    __nv_bfloat16* sAl = smem + 32 * PAD;

    const int tid  = threadIdx.x;
    const int lane = tid & 31;
    const int w    = tid >> 5;
    const int m0   = blockIdx.x * 32;

    for (int i = tid; i < 32 * 32; i += 256) {
        int r = i >> 5, c4 = i & 31;
        float4 v = make_float4(0.f, 0.f, 0.f, 0.f);
        if (m0 + r < M) v = *(const float4*)(A + (size_t)(m0 + r) * 128 + c4 * 4);
        __nv_bfloat16 hx, lx, hy, ly, hz, lz, hw, lw;
        split2(v.x, hx, lx); split2(v.y, hy, ly);
        split2(v.z, hz, lz); split2(v.w, hw, lw);
        int base = r * PAD + c4 * 4;
        *(__nv_bfloat162*)(sAh + base)     = __nv_bfloat162(hx, hy);
        *(__nv_bfloat162*)(sAh + base + 2) = __nv_bfloat162(hz, hw);
        *(__nv_bfloat162*)(sAl + base)     = __nv_bfloat162(lx, ly);
        *(__nv_bfloat162*)(sAl + base + 2) = __nv_bfloat162(lz, lw);
    }
    __syncthreads();

    const uint32_t uAh = smem_u32(sAh), uAl = smem_u32(sAl);
    uint32_t offA[2];
#pragma unroll
    for (int mt = 0; mt < 2; mt++) {
        int row = mt * 16 + (lane & 15);
        offA[mt] = (uint32_t)(row * PAD + (lane >> 4) * 8) * 2;
    }

    const int wslice = w >> 1, whalf = w & 1;

    float acc[2][6][4];
#pragma unroll
    for (int a = 0; a < 2; a++)
#pragma unroll
        for (int b = 0; b < 6; b++)
#pragma unroll
            for (int c = 0; c < 4; c++) acc[a][b][c] = 0.f;

#pragma unroll
    for (int ks = 0; ks < 8; ks++) {
        const uint32_t kb = ks * 32;
        uint32_t bh[3][4], bl[3][4];
#pragma unroll
        for (int g = 0; g < 3; g++) {
            size_t f = (((size_t)g * 4 + wslice) * 16 + ks * 2 + whalf) * 32 + lane;
            uint4 vh = __ldg(BfH + f);
            uint4 vl = __ldg(BfL + f);
            bh[g][0] = vh.x; bh[g][1] = vh.y; bh[g][2] = vh.z; bh[g][3] = vh.w;
            bl[g][0] = vl.x; bl[g][1] = vl.y; bl[g][2] = vl.z; bl[g][3] = vl.w;
        }
#pragma unroll
        for (int mt = 0; mt < 2; mt++) {
            uint32_t ah[4], al[4];
            ldsm_x4(ah, uAh + offA[mt] + kb);
            ldsm_x4(al, uAl + offA[mt] + kb);
#pragma unroll
            for (int nt = 0; nt < 6; nt++) {
                const int g = nt >> 1, s = (nt & 1) * 2;
                mma_bf16(acc[mt][nt], ah, bh[g][s], bh[g][s + 1]);
            }
#pragma unroll
            for (int nt = 0; nt < 6; nt++) {
                const int g = nt >> 1, s = (nt & 1) * 2;
                mma_bf16(acc[mt][nt], al, bh[g][s], bh[g][s + 1]);
            }
#pragma unroll
            for (int nt = 0; nt < 6; nt++) {
                const int g = nt >> 1, s = (nt & 1) * 2;
                mma_bf16(acc[mt][nt], ah, bl[g][s], bl[g][s + 1]);
            }
        }
    }

#pragma unroll
    for (int mt = 0; mt < 2; mt++) {
        int row0 = m0 + mt * 16 + (lane >> 2);
#pragma unroll
        for (int j = 0; j < 2; j++) {
            int c = w * 16 + j * 8 + (lane & 3) * 2;   // 0..127
            float br0 = b_ih[c],       br1 = b_ih[c + 1];
            float bz0 = b_ih[128 + c], bz1 = b_ih[128 + c + 1];
            float bn0 = b_ih[256 + c], bn1 = b_ih[256 + c + 1];
#pragma unroll
            for (int rr = 0; rr < 2; rr++) {
                int row = row0 + rr * 8;
                if (row >= M) continue;
                const float* ghr = gh + (size_t)row * 384;
                float2 ghr_r = *(const float2*)(ghr + c);
                float2 ghr_z = *(const float2*)(ghr + 128 + c);
                float2 ghr_n = *(const float2*)(ghr + 256 + c);
                float2 hv    = *(const float2*)(h + (size_t)row * 128 + c);
                int q = rr * 2;
                float ir0 = acc[mt][0 + j][q]     + br0, ir1 = acc[mt][0 + j][q + 1] + br1;
                float iz0 = acc[mt][2 + j][q]     + bz0, iz1 = acc[mt][2 + j][q + 1] + bz1;
                float in0 = acc[mt][4 + j][q]     + bn0, in1 = acc[mt][4 + j][q + 1] + bn1;
                float r0 = sigmoidf_(ir0 + ghr_r.x), r1 = sigmoidf_(ir1 + ghr_r.y);
                float z0 = sigmoidf_(iz0 + ghr_z.x), z1 = sigmoidf_(iz1 + ghr_z.y);
                float n0 = tanhf(in0 + r0 * ghr_n.x), n1 = tanhf(in1 + r1 * ghr_n.y);
                float o0 = (1.f - z0) * n0 + z0 * hv.x;
                float o1 = (1.f - z1) * n1 + z1 * hv.y;
                *(float2*)(h + (size_t)row * 128 + c) = make_float2(o0, o1);
                __nv_bfloat16 h0, l0, h1, l1;
                split2(o0, h0, l0); split2(o1, h1, l1);
                *(__nv_bfloat162*)(g_h_hi + (size_t)row * 128 + c) = __nv_bfloat162(h0, h1);
                *(__nv_bfloat162*)(g_h_lo + (size_t)row * 128 + c) = __nv_bfloat162(l0, l1);
            }
        }
    }
}

// ---------------- launch (R14 base; Ht chunked 4/2/2 to shrink exposed scatter) ----------------
extern "C" void kernel_launch(void* const* d_in, const int* in_sizes, int n_in,
                              void* d_out, int out_size)
{
    const int*   x          = (const int*)d_in[0];
    const int*   edge_index = (const int*)d_in[1];
    const int*   edge_type  = (const int*)d_in[2];
    const int*   node_type  = (const int*)d_in[3];
    const float* emb        = (const float*)d_in[4];
    const float* W_rel      = (const float*)d_in[5];
    const float* b_node     = (const float*)d_in[6];
    const float* W_ih       = (const float*)d_in[7];
    const float* W_hh       = (const float*)d_in[8];
    const float* b_ih       = (const float*)d_in[9];
    const float* b_hh       = (const float*)d_in[10];
    float* h = (float*)d_out;

    float *Ht, *aggr, *gh;
    cudaGetSymbolAddress((void**)&Ht,   g_Ht);
    cudaGetSymbolAddress((void**)&aggr, g_aggr);
    cudaGetSymbolAddress((void**)&gh,   g_gh);
    __nv_bfloat16 *h_hi, *h_lo;
    cudaGetSymbolAddress((void**)&h_hi, g_h_hi);
    cudaGetSymbolAddress((void**)&h_lo, g_h_lo);
    uint4 *wrF_hi, *wrF_lo, *wihF_hi, *wihF_lo, *whhF_hi, *whhF_lo;
    cudaGetSymbolAddress((void**)&wrF_hi, g_wrelF_hi);
    cudaGetSymbolAddress((void**)&wrF_lo, g_wrelF_lo);
    cudaGetSymbolAddress((void**)&wihF_hi, g_wihF_hi);
    cudaGetSymbolAddress((void**)&wihF_lo, g_wihF_lo);
    cudaGetSymbolAddress((void**)&whhF_hi, g_whhF_hi);
    cudaGetSymbolAddress((void**)&whhF_lo, g_whhF_lo);

    cudaFuncSetAttribute(gemm_mma_kernel,    cudaFuncAttributeMaxDynamicSharedMemorySize, SM_BYTES);
    cudaFuncSetAttribute(weight_prep_kernel, cudaFuncAttributeMaxDynamicSharedMemorySize, SM_BYTES);
    cudaFuncSetAttribute(gru_fused_kernel,   cudaFuncAttributeMaxDynamicSharedMemorySize, SMF_BYTES);

    // one-time host-side infra (1 stream, 6 events)
    static cudaStream_t s2 = nullptr;
    static cudaEvent_t evFork = nullptr, evJoinSetup, evHtA, evHtB, evHtC, evScat;
    if (!s2) {
        cudaStreamCreateWithFlags(&s2, cudaStreamNonBlocking);
        cudaEventCreateWithFlags(&evFork,      cudaEventDisableTiming);
        cudaEventCreateWithFlags(&evJoinSetup, cudaEventDisableTiming);
        cudaEventCreateWithFlags(&evHtA,       cudaEventDisableTiming);
        cudaEventCreateWithFlags(&evHtB,       cudaEventDisableTiming);
        cudaEventCreateWithFlags(&evHtC,       cudaEventDisableTiming);
        cudaEventCreateWithFlags(&evScat,      cudaEventDisableTiming);
    }

    const int elem_blocks = (N_NODES * 32 + 255) / 256;
    const int csr4_blocks = (4 * N_NODES * 32 + 255) / 256;
    const int csr2_blocks = (2 * N_NODES * 32 + 255) / 256;
    const int edge_blocks = (N_EDGES + 255) / 256;
    const int mtiles  = (N_NODES + 127) / 128;
    const int mtiles32 = (N_NODES + 31) / 32;
    dim3 gHt4(mtiles, 4);     // chunk A: types 0..3
    dim3 gHt2(mtiles, 2);     // chunks B/C: 2 types each
    dim3 gGru(mtiles, 3);

    // ---- setup: sort on s2; unified weight prep + embed on main ----
    cudaEventRecord(evFork, 0);
    cudaStreamWaitEvent(s2, evFork, 0);

    zero_hist_kernel<<<(NKEYS + 1023) / 1024, 1024, 0, s2>>>();
    hist_kernel<<<edge_blocks, 256, 0, s2>>>(edge_index, edge_type);
    scan1_kernel<<<NBLK, SCAN_B, 0, s2>>>();
    scan2_kernel<<<1, 1024, 0, s2>>>();
    scan3_kernel<<<NBLK, SCAN_B, 0, s2>>>();
    reorder_kernel<<<edge_blocks, 256, 0, s2>>>(edge_index, edge_type);
    cudaEventRecord(evJoinSetup, s2);

    weight_prep_kernel<<<14, 256, SM_BYTES>>>(W_rel, W_ih, W_hh);
    embed_kernel<<<elem_blocks, 256>>>(x, emb, h);

    cudaStreamWaitEvent(0, evJoinSetup, 0);   // R14 behavior (cost measured ~0)

    for (int it = 0; it < 5; it++) {
        // fork: h (and split h) ready on stream 0
        cudaEventRecord(evFork, 0);
        cudaStreamWaitEvent(s2, evFork, 0);

        // s2: init_aggr -> gh (concurrent tensor work fills tails)
        init_aggr_kernel<<<elem_blocks, 256, 0, s2>>>(node_type, b_node);
        gemm_mma_kernel<<<gGru, 256, SM_BYTES, s2>>>(h_hi, h_lo, whhF_hi, whhF_lo,
                                                     gh, b_hh, N_NODES, 3 * D, 128);

        // main: Ht chunks A (types 0..3), B (4..5), C (6..7)
        gemm_mma_kernel<<<gHt4, 256, SM_BYTES>>>(h_hi, h_lo, wrF_hi, wrF_lo, Ht, nullptr,
                                                 N_NODES, D, (size_t)N_NODES * D);
        cudaEventRecord(evHtA, 0);
        gemm_mma_kernel<<<gHt2, 256, SM_BYTES>>>(h_hi, h_lo, wrF_hi + 4 * 2048,
                                                 wrF_lo + 4 * 2048,
                                                 Ht + (size_t)4 * N_NODES * D, nullptr,
                                                 N_NODES, D, (size_t)N_NODES * D);
        cudaEventRecord(evHtB, 0);
        gemm_mma_kernel<<<gHt2, 256, SM_BYTES>>>(h_hi, h_lo, wrF_hi + 6 * 2048,
                                                 wrF_lo + 6 * 2048,
                                                 Ht + (size_t)6 * N_NODES * D, nullptr,
                                                 N_NODES, D, (size_t)N_NODES * D);
        cudaEventRecord(evHtC, 0);

        // s2: scatters pipelined behind their Ht chunks (ordered after init+gh)
        cudaStreamWaitEvent(s2, evHtA, 0);
        scatter_csr_kernel<<<csr4_blocks, 256, 0, s2>>>(0, 4);
        cudaStreamWaitEvent(s2, evHtB, 0);
        scatter_csr_kernel<<<csr2_blocks, 256, 0, s2>>>(4, 2);
        cudaStreamWaitEvent(s2, evHtC, 0);
        scatter_csr_kernel<<<csr2_blocks, 256, 0, s2>>>(6, 2);
        cudaEventRecord(evScat, s2);

        // main: fused gi GEMM + GRU gates (gh done before evScat by s2 ordering)
        cudaStreamWaitEvent(0, evScat, 0);
        gru_fused_kernel<<<mtiles32, 256, SMF_BYTES>>>(aggr, wihF_hi, wihF_lo,
                                                       gh, b_ih, h, N_NODES);
    }
}

// round 17
// speedup vs baseline: 1.1458x; 1.1458x over previous
#include <cuda_runtime.h>
#include <cuda_fp16.h>
#include <cstdint>

#define N_NODES 50000
#define N_EDGES 800000
#define D       128
#define T_REL   8
#define PAD     136   // fp16 elems per smem row (272B = 17 x 16B chunks)
#define NKEYS   (N_NODES * T_REL)        // 400000
#define SCAN_B  512
#define NBLK    ((NKEYS + SCAN_B - 1) / SCAN_B)   // 782

// ---------------- scratch (static device globals; no allocation) ----------------
__device__ float g_Ht  [(size_t)N_NODES * T_REL * D];   // 204.8 MB, layout [t][n][f] == [key][f]
__device__ float g_aggr[(size_t)N_NODES * D];           //  25.6 MB
__device__ float g_gh  [(size_t)N_NODES * 3 * D];       //  76.8 MB

__device__ __half g_h16[(size_t)N_NODES * D];           // fp16 h (GEMM input only)

// B fragments: per tile 4 wn x 8 ks x 2 p x 32 lanes = 2048 uint4 (32 KB)
__device__ uint4 g_wrelF_hi[T_REL * 2048];
__device__ uint4 g_wrelF_lo[T_REL * 2048];
__device__ uint4 g_wihF_hi[3 * 2048];
__device__ uint4 g_wihF_lo[3 * 2048];
__device__ uint4 g_whhF_hi[3 * 2048];
__device__ uint4 g_whhF_lo[3 * 2048];

// edge sort scratch (type-major keys: key = type*N + src)
__device__ int g_hist[NKEYS];
__device__ int g_off [NKEYS];    // after reorder: END offset per key (CSR)
__device__ int g_bsum[1024];
__device__ int g_sdst[N_EDGES];

// ---------------- helpers ----------------
__device__ __forceinline__ uint32_t smem_u32(const void* p) {
    uint32_t a;
    asm("{ .reg .u64 t; cvta.to.shared.u64 t, %1; cvt.u32.u64 %0, t; }" : "=r"(a) : "l"(p));
    return a;
}
__device__ __forceinline__ void split2h(float v, __half& hi, __half& lo) {
    hi = __float2half_rn(v);
    lo = __float2half_rn(v - __half2float(hi));
}
__device__ __forceinline__ void ldsm_x4(uint32_t* r, uint32_t addr) {
    asm volatile("ldmatrix.sync.aligned.m8n8.x4.shared.b16 {%0,%1,%2,%3}, [%4];"
                 : "=r"(r[0]), "=r"(r[1]), "=r"(r[2]), "=r"(r[3]) : "r"(addr));
}
__device__ __forceinline__ void mma_f16(float* c, const uint32_t* a, uint32_t b0, uint32_t b1) {
    asm volatile("mma.sync.aligned.m16n8k16.row.col.f32.f16.f16.f32 "
                 "{%0,%1,%2,%3}, {%4,%5,%6,%7}, {%8,%9}, {%0,%1,%2,%3};"
                 : "+f"(c[0]), "+f"(c[1]), "+f"(c[2]), "+f"(c[3])
                 : "r"(a[0]), "r"(a[1]), "r"(a[2]), "r"(a[3]), "r"(b0), "r"(b1));
}
__device__ __forceinline__ float sigmoidf_(float v) { return 1.f / (1.f + expf(-v)); }

// ---------------- small kernels ----------------
__global__ void embed_kernel(const int* __restrict__ x, const float* __restrict__ emb,
                             float* __restrict__ h)
{
    int g = blockIdx.x * blockDim.x + threadIdx.x;
    if (g >= N_NODES * (D / 4)) return;
    int n = g >> 5, c = g & 31;
    float4 v = ((const float4*)emb)[(size_t)x[n] * 32 + c];
    ((float4*)h)[n * 32 + c] = v;
    size_t base = (size_t)n * D + c * 4;
    *(__half2*)(g_h16 + base)     = __half2(__float2half_rn(v.x), __float2half_rn(v.y));
    *(__half2*)(g_h16 + base + 2) = __half2(__float2half_rn(v.z), __float2half_rn(v.w));
}

__global__ void init_aggr_kernel(const int* __restrict__ node_type,
                                 const float* __restrict__ b_node)
{
    int g = blockIdx.x * blockDim.x + threadIdx.x;
    if (g >= N_NODES * (D / 4)) return;
    int n = g >> 5, c = g & 31;
    ((float4*)g_aggr)[n * 32 + c] = ((const float4*)b_node)[(size_t)node_type[n] * 32 + c];
}

// ---------------- edge counting sort, type-major (once per launch) ----------------
__global__ void zero_hist_kernel()
{
    int i = blockIdx.x * blockDim.x + threadIdx.x;
    if (i < NKEYS) g_hist[i] = 0;
}

__global__ void hist_kernel(const int* __restrict__ edge_index,
                            const int* __restrict__ edge_type)
{
    int e = blockIdx.x * blockDim.x + threadIdx.x;
    if (e >= N_EDGES) return;
    int key = edge_type[e] * N_NODES + edge_index[e];
    atomicAdd(&g_hist[key], 1);
}

__global__ void scan1_kernel()
{
    __shared__ int s[SCAN_B];
    int b = blockIdx.x, t = threadIdx.x, i = b * SCAN_B + t;
    int v = (i < NKEYS) ? g_hist[i] : 0;
    s[t] = v;
    __syncthreads();
#pragma unroll
    for (int o = 1; o < SCAN_B; o <<= 1) {
        int x = (t >= o) ? s[t - o] : 0;
        __syncthreads();
        if (t >= o) s[t] += x;
        __syncthreads();
    }
    if (i < NKEYS) g_off[i] = s[t] - v;
    if (t == SCAN_B - 1) g_bsum[b] = s[t];
}

__global__ void scan2_kernel()
{
    __shared__ int s[1024];
    int t = threadIdx.x;
    int v = (t < NBLK) ? g_bsum[t] : 0;
    s[t] = v;
    __syncthreads();
#pragma unroll
    for (int o = 1; o < 1024; o <<= 1) {
        int x = (t >= o) ? s[t - o] : 0;
        __syncthreads();
        if (t >= o) s[t] += x;
        __syncthreads();
    }
    if (t < NBLK) g_bsum[t] = s[t] - v;
}

__global__ void scan3_kernel()
{
    int b = blockIdx.x, i = b * SCAN_B + threadIdx.x;
    if (i < NKEYS) g_off[i] += g_bsum[b];
}

__global__ void reorder_kernel(const int* __restrict__ edge_index,
                               const int* __restrict__ edge_type)
{
    int e = blockIdx.x * blockDim.x + threadIdx.x;
    if (e >= N_EDGES) return;
    int key = edge_type[e] * N_NODES + edge_index[e];
    int pos = atomicAdd(&g_off[key], 1);   // leaves g_off[key] = END offset
    g_sdst[pos] = edge_index[N_EDGES + e];
}

// ---------------- CSR scatter for 4 types: warp per key ----------------
__global__ void scatter_csr_kernel(int tBase)
{
    int gw = (blockIdx.x * blockDim.x + threadIdx.x) >> 5;
    int lane = threadIdx.x & 31;
    if (gw >= 4 * N_NODES) return;
    int key = tBase * N_NODES + gw;
    int start = (key == 0) ? 0 : __ldg(g_off + key - 1);
    int end   = __ldg(g_off + key);
    if (start == end) return;
    float4 v = __ldg(((const float4*)g_Ht) + (size_t)key * 32 + lane);
    for (int e = start; e < end; e++) {
        int dst = __ldg(g_sdst + e);
        float* p = g_aggr + (size_t)dst * D + lane * 4;
        asm volatile("red.global.add.v4.f32 [%0], {%1, %2, %3, %4};"
                     :: "l"(p), "f"(v.x), "f"(v.y), "f"(v.z), "f"(v.w) : "memory");
    }
}

// ---------------- unified weight prep: fp32 -> fp16 hi/lo -> fragments, ONE launch ----------------
// grid = 14 blocks: 0..7 = W_rel tiles (transposed), 8..10 = W_ih, 11..13 = W_hh.
#define SMW_BYTES (2 * 128 * PAD * 2)

__global__ void weight_prep_kernel(const float* __restrict__ W_rel,
                                   const float* __restrict__ W_ih,
                                   const float* __restrict__ W_hh)
{
    extern __shared__ __half smemw[];
    __half* sBh = smemw;
    __half* sBl = smemw + 128 * PAD;

    const int bT = blockIdx.x;
    const int tid = threadIdx.x, lane = tid & 31, w = tid >> 5;

    const float* src;
    uint4 *dstH, *dstL;
    bool trans;
    if (bT < 8) {
        src = W_rel + (size_t)bT * 128 * 128;
        dstH = g_wrelF_hi + (size_t)bT * 2048;
        dstL = g_wrelF_lo + (size_t)bT * 2048;
        trans = true;
    } else if (bT < 11) {
        int g = bT - 8;
        src = W_ih + (size_t)g * 128 * 128;
        dstH = g_wihF_hi + (size_t)g * 2048;
        dstL = g_wihF_lo + (size_t)g * 2048;
        trans = false;
    } else {
        int g = bT - 11;
        src = W_hh + (size_t)g * 128 * 128;
        dstH = g_whhF_hi + (size_t)g * 2048;
        dstL = g_whhF_lo + (size_t)g * 2048;
        trans = false;
    }

    for (int i = tid; i < 128 * 128; i += 256) {
        float v = src[i];
        int row, col;
        if (trans) { row = i & 127; col = i >> 7; }
        else       { row = i >> 7; col = i & 127; }
        __half hi, lo;
        split2h(v, hi, lo);
        sBh[row * PAD + col] = hi;
        sBl[row * PAD + col] = lo;
    }
    __syncthreads();

    const uint32_t uBh = smem_u32(sBh), uBl = smem_u32(sBl);
    const int wn = w >> 1;
    for (int ksi = 0; ksi < 4; ksi++) {
        int ks = (w & 1) * 4 + ksi;
#pragma unroll
        for (int p = 0; p < 2; p++) {
            int row = wn * 32 + p * 16 + (lane & 7) + ((lane >> 4) << 3);
            uint32_t off = (uint32_t)(row * PAD + ((lane >> 3) & 1) * 8) * 2 + ks * 32;
            uint32_t r[4];
            ldsm_x4(r, uBh + off);
            dstH[((size_t)wn * 16 + ks * 2 + p) * 32 + lane] = make_uint4(r[0], r[1], r[2], r[3]);
            ldsm_x4(r, uBl + off);
            dstL[((size_t)wn * 16 + ks * 2 + p) * 32 + lane] = make_uint4(r[0], r[1], r[2], r[3]);
        }
    }
}

// ---------------- fp16 2-pass GEMM (Ht / gh): A single fp16, 128x128 tile ----------------
#define SM_BYTES (128 * PAD * 2)

__global__ __launch_bounds__(256, 2)
void gemm_mma_kernel(const __half* __restrict__ A16,
                     const uint4* __restrict__ BfH,
                     const uint4* __restrict__ BfL,
                     float* __restrict__ C,
                     const float* __restrict__ bias,
                     int M, int ldc, size_t cBlockStride)
{
    extern __shared__ __half smem[];
    __half* sA = smem;

    const int tid  = threadIdx.x;
    const int lane = tid & 31;
    const int wid  = tid >> 5;
    const int warp_m = wid & 1;
    const int warp_n = wid >> 1;
    const int m0 = blockIdx.x * 128;
    const int bT = blockIdx.y;

    // ---- copy A (fp16) into smem ----
    {
        const uint4 zero = make_uint4(0, 0, 0, 0);
        for (int i = tid; i < 128 * 16; i += 256) {
            int r = i >> 4, c8 = i & 15;
            uint4 v = zero;
            if (m0 + r < M) v = *(const uint4*)(A16 + (size_t)(m0 + r) * 128 + c8 * 8);
            *(uint4*)(sA + r * PAD + c8 * 8) = v;
        }
    }
    __syncthreads();

    const uint32_t uA = smem_u32(sA);
    uint32_t offA[4];
#pragma unroll
    for (int mt = 0; mt < 4; mt++) {
        int row = warp_m * 64 + mt * 16 + (lane & 15);
        offA[mt] = (uint32_t)(row * PAD + (lane >> 4) * 8) * 2;
    }

    const uint4* bfh = BfH + ((size_t)bT * 4 + warp_n) * 16 * 32 + lane;
    const uint4* bfl = BfL + ((size_t)bT * 4 + warp_n) * 16 * 32 + lane;

    float acc[4][4][4];
#pragma unroll
    for (int a = 0; a < 4; a++)
#pragma unroll
        for (int b = 0; b < 4; b++)
#pragma unroll
            for (int c = 0; c < 4; c++) acc[a][b][c] = 0.f;

    uint4 ph0 = __ldg(bfh + 0 * 32), ph1 = __ldg(bfh + 1 * 32);
    uint4 pl0 = __ldg(bfl + 0 * 32), pl1 = __ldg(bfl + 1 * 32);

#pragma unroll
    for (int ks = 0; ks < 8; ks++) {
        const uint32_t kb = ks * 32;
        uint32_t bh[2][4] = {{ph0.x, ph0.y, ph0.z, ph0.w}, {ph1.x, ph1.y, ph1.z, ph1.w}};
        uint32_t bl[2][4] = {{pl0.x, pl0.y, pl0.z, pl0.w}, {pl1.x, pl1.y, pl1.z, pl1.w}};
        if (ks < 7) {
            ph0 = __ldg(bfh + ((ks + 1) * 2 + 0) * 32);
            ph1 = __ldg(bfh + ((ks + 1) * 2 + 1) * 32);
            pl0 = __ldg(bfl + ((ks + 1) * 2 + 0) * 32);
            pl1 = __ldg(bfl + ((ks + 1) * 2 + 1) * 32);
        }
#pragma unroll
        for (int mt = 0; mt < 4; mt++) {
            uint32_t ah[4];
            ldsm_x4(ah, uA + offA[mt] + kb);
#pragma unroll
            for (int nt = 0; nt < 4; nt++) {
                const int p = nt >> 1, s = (nt & 1) * 2;
                mma_f16(acc[mt][nt], ah, bh[p][s], bh[p][s + 1]);   // a*B_hi
            }
#pragma unroll
            for (int nt = 0; nt < 4; nt++) {
                const int p = nt >> 1, s = (nt & 1) * 2;
                mma_f16(acc[mt][nt], ah, bl[p][s], bl[p][s + 1]);   // a*B_lo
            }
        }
    }

    float* Cb = C + (size_t)bT * cBlockStride;
#pragma unroll
    for (int mt = 0; mt < 4; mt++) {
        int row0 = m0 + warp_m * 64 + mt * 16 + (lane >> 2);
#pragma unroll
        for (int nt = 0; nt < 4; nt++) {
            int col = warp_n * 32 + nt * 8 + (lane & 3) * 2;
            float b0 = 0.f, b1 = 0.f;
            if (bias) { b0 = bias[bT * 128 + col]; b1 = bias[bT * 128 + col + 1]; }
            if (row0 < M) {
                float2 v = make_float2(acc[mt][nt][0] + b0, acc[mt][nt][1] + b1);
                *(float2*)(Cb + (size_t)row0 * ldc + col) = v;
            }
            if (row0 + 8 < M) {
                float2 v = make_float2(acc[mt][nt][2] + b0, acc[mt][nt][3] + b1);
                *(float2*)(Cb + (size_t)(row0 + 8) * ldc + col) = v;
            }
        }
    }
}

// ---------------- fused gi GEMM + GRU gates (fp16 2-pass; emits fp16 h) ----------------
#define SMF_BYTES (32 * PAD * 2)

__global__ __launch_bounds__(256, 2)
void gru_fused_kernel(const float* __restrict__ A,          // aggr [M,128] fp32 -> fp16 here
                      const uint4* __restrict__ BfH,        // wihF hi (3 tiles)
                      const uint4* __restrict__ BfL,
                      const float* __restrict__ gh,         // [M, 384] (b_hh added)
                      const float* __restrict__ b_ih,       // [384]
                      float* __restrict__ h,                // [M, 128] in/out (fp32)
                      int M)
{
    extern __shared__ __half smem[];
    __half* sA = smem;

    const int tid  = threadIdx.x;
    const int lane = tid & 31;
    const int w    = tid >> 5;
    const int m0   = blockIdx.x * 32;

    for (int i = tid; i < 32 * 32; i += 256) {
        int r = i >> 5, c4 = i & 31;
        float4 v = make_float4(0.f, 0.f, 0.f, 0.f);
        if (m0 + r < M) v = *(const float4*)(A + (size_t)(m0 + r) * 128 + c4 * 4);
        int base = r * PAD + c4 * 4;
        *(__half2*)(sA + base)     = __half2(__float2half_rn(v.x), __float2half_rn(v.y));
        *(__half2*)(sA + base + 2) = __half2(__float2half_rn(v.z), __float2half_rn(v.w));
    }
    __syncthreads();

    const uint32_t uA = smem_u32(sA);
    uint32_t offA[2];
#pragma unroll
    for (int mt = 0; mt < 2; mt++) {
        int row = mt * 16 + (lane & 15);
        offA[mt] = (uint32_t)(row * PAD + (lane >> 4) * 8) * 2;
    }

    const int wslice = w >> 1, whalf = w & 1;

    float acc[2][6][4];
#pragma unroll
    for (int a = 0; a < 2; a++)
#pragma unroll
        for (int b = 0; b < 6; b++)
#pragma unroll
            for (int c = 0; c < 4; c++) acc[a][b][c] = 0.f;

#pragma unroll
    for (int ks = 0; ks < 8; ks++) {
        const uint32_t kb = ks * 32;
        uint32_t bh[3][4], bl[3][4];
#pragma unroll
        for (int g = 0; g < 3; g++) {
            size_t f = (((size_t)g * 4 + wslice) * 16 + ks * 2 + whalf) * 32 + lane;
            uint4 vh = __ldg(BfH + f);
            uint4 vl = __ldg(BfL + f);
            bh[g][0] = vh.x; bh[g][1] = vh.y; bh[g][2] = vh.z; bh[g][3] = vh.w;
            bl[g][0] = vl.x; bl[g][1] = vl.y; bl[g][2] = vl.z; bl[g][3] = vl.w;
        }
#pragma unroll
        for (int mt = 0; mt < 2; mt++) {
            uint32_t ah[4];
            ldsm_x4(ah, uA + offA[mt] + kb);
#pragma unroll
            for (int nt = 0; nt < 6; nt++) {
                const int g = nt >> 1, s = (nt & 1) * 2;
                mma_f16(acc[mt][nt], ah, bh[g][s], bh[g][s + 1]);
            }
#pragma unroll
            for (int nt = 0; nt < 6; nt++) {
                const int g = nt >> 1, s = (nt & 1) * 2;
                mma_f16(acc[mt][nt], ah, bl[g][s], bl[g][s + 1]);
            }
        }
    }

#pragma unroll
    for (int mt = 0; mt < 2; mt++) {
        int row0 = m0 + mt * 16 + (lane >> 2);
#pragma unroll
        for (int j = 0; j < 2; j++) {
            int c = w * 16 + j * 8 + (lane & 3) * 2;   // 0..127
            float br0 = b_ih[c],       br1 = b_ih[c + 1];
            float bz0 = b_ih[128 + c], bz1 = b_ih[128 + c + 1];
            float bn0 = b_ih[256 + c], bn1 = b_ih[256 + c + 1];
#pragma unroll
            for (int rr = 0; rr < 2; rr++) {
                int row = row0 + rr * 8;
                if (row >= M) continue;
                const float* ghr = gh + (size_t)row * 384;
                float2 ghr_r = *(const float2*)(ghr + c);
                float2 ghr_z = *(const float2*)(ghr + 128 + c);
                float2 ghr_n = *(const float2*)(ghr + 256 + c);
                float2 hv    = *(const float2*)(h + (size_t)row * 128 + c);
                int q = rr * 2;
                float ir0 = acc[mt][0 + j][q]     + br0, ir1 = acc[mt][0 + j][q + 1] + br1;
                float iz0 = acc[mt][2 + j][q]     + bz0, iz1 = acc[mt][2 + j][q + 1] + bz1;
                float in0 = acc[mt][4 + j][q]     + bn0, in1 = acc[mt][4 + j][q + 1] + bn1;
                float r0 = sigmoidf_(ir0 + ghr_r.x), r1 = sigmoidf_(ir1 + ghr_r.y);
                float z0 = sigmoidf_(iz0 + ghr_z.x), z1 = sigmoidf_(iz1 + ghr_z.y);
                float n0 = tanhf(in0 + r0 * ghr_n.x), n1 = tanhf(in1 + r1 * ghr_n.y);
                float o0 = (1.f - z0) * n0 + z0 * hv.x;
                float o1 = (1.f - z1) * n1 + z1 * hv.y;
                *(float2*)(h + (size_t)row * 128 + c) = make_float2(o0, o1);
                *(__half2*)(g_h16 + (size_t)row * 128 + c) =
                    __half2(__float2half_rn(o0), __float2half_rn(o1));
            }
        }
    }
}

// ---------------- launch (R14 schedule, fp16 path) ----------------
extern "C" void kernel_launch(void* const* d_in, const int* in_sizes, int n_in,
                              void* d_out, int out_size)
{
    const int*   x          = (const int*)d_in[0];
    const int*   edge_index = (const int*)d_in[1];
    const int*   edge_type  = (const int*)d_in[2];
    const int*   node_type  = (const int*)d_in[3];
    const float* emb        = (const float*)d_in[4];
    const float* W_rel      = (const float*)d_in[5];
    const float* b_node     = (const float*)d_in[6];
    const float* W_ih       = (const float*)d_in[7];
    const float* W_hh       = (const float*)d_in[8];
    const float* b_ih       = (const float*)d_in[9];
    const float* b_hh       = (const float*)d_in[10];
    float* h = (float*)d_out;

    float *Ht, *aggr, *gh;
    cudaGetSymbolAddress((void**)&Ht,   g_Ht);
    cudaGetSymbolAddress((void**)&aggr, g_aggr);
    cudaGetSymbolAddress((void**)&gh,   g_gh);
    __half* h16;
    cudaGetSymbolAddress((void**)&h16, g_h16);
    uint4 *wrF_hi, *wrF_lo, *wihF_hi, *wihF_lo, *whhF_hi, *whhF_lo;
    cudaGetSymbolAddress((void**)&wrF_hi, g_wrelF_hi);
    cudaGetSymbolAddress((void**)&wrF_lo, g_wrelF_lo);
    cudaGetSymbolAddress((void**)&wihF_hi, g_wihF_hi);
    cudaGetSymbolAddress((void**)&wihF_lo, g_wihF_lo);
    cudaGetSymbolAddress((void**)&whhF_hi, g_whhF_hi);
    cudaGetSymbolAddress((void**)&whhF_lo, g_whhF_lo);

    cudaFuncSetAttribute(gemm_mma_kernel,    cudaFuncAttributeMaxDynamicSharedMemorySize, SM_BYTES);
    cudaFuncSetAttribute(weight_prep_kernel, cudaFuncAttributeMaxDynamicSharedMemorySize, SMW_BYTES);
    cudaFuncSetAttribute(gru_fused_kernel,   cudaFuncAttributeMaxDynamicSharedMemorySize, SMF_BYTES);

    // one-time host-side infra (1 stream, 5 events — proven footprint)
    static cudaStream_t s2 = nullptr;
    static cudaEvent_t evFork = nullptr, evJoinSetup, evHtA, evHtB, evScat;
    if (!s2) {
        cudaStreamCreateWithFlags(&s2, cudaStreamNonBlocking);
        cudaEventCreateWithFlags(&evFork,      cudaEventDisableTiming);
        cudaEventCreateWithFlags(&evJoinSetup, cudaEventDisableTiming);
        cudaEventCreateWithFlags(&evHtA,       cudaEventDisableTiming);
        cudaEventCreateWithFlags(&evHtB,       cudaEventDisableTiming);
        cudaEventCreateWithFlags(&evScat,      cudaEventDisableTiming);
    }

    const int elem_blocks = (N_NODES * 32 + 255) / 256;
    const int csr_blocks  = (4 * N_NODES * 32 + 255) / 256;
    const int edge_blocks = (N_EDGES + 255) / 256;
    const int mtiles  = (N_NODES + 127) / 128;
    const int mtiles32 = (N_NODES + 31) / 32;
    dim3 gHt4(mtiles, 4);     // 4 types per chunk
    dim3 gGru(mtiles, 3);

    // ---- setup: sort on s2; unified weight prep + embed on main ----
    cudaEventRecord(evFork, 0);
    cudaStreamWaitEvent(s2, evFork, 0);

    zero_hist_kernel<<<(NKEYS + 1023) / 1024, 1024, 0, s2>>>();
    hist_kernel<<<edge_blocks, 256, 0, s2>>>(edge_index, edge_type);
    scan1_kernel<<<NBLK, SCAN_B, 0, s2>>>();
    scan2_kernel<<<1, 1024, 0, s2>>>();
    scan3_kernel<<<NBLK, SCAN_B, 0, s2>>>();
    reorder_kernel<<<edge_blocks, 256, 0, s2>>>(edge_index, edge_type);
    cudaEventRecord(evJoinSetup, s2);

    weight_prep_kernel<<<14, 256, SMW_BYTES>>>(W_rel, W_ih, W_hh);
    embed_kernel<<<elem_blocks, 256>>>(x, emb, h);

    cudaStreamWaitEvent(0, evJoinSetup, 0);

    for (int it = 0; it < 5; it++) {
        // fork: h (and fp16 h) ready on stream 0
        cudaEventRecord(evFork, 0);
        cudaStreamWaitEvent(s2, evFork, 0);

        // s2: init_aggr -> gh = h @ W_hh^T + b_hh (concurrent tensor work fills tails)
        init_aggr_kernel<<<elem_blocks, 256, 0, s2>>>(node_type, b_node);
        gemm_mma_kernel<<<gGru, 256, SM_BYTES, s2>>>(h16, whhF_hi, whhF_lo,
                                                     gh, b_hh, N_NODES, 3 * D, 128);

        // main: Ht chunk A (types 0..3), then chunk B (types 4..7)
        gemm_mma_kernel<<<gHt4, 256, SM_BYTES>>>(h16, wrF_hi, wrF_lo, Ht, nullptr,
                                                 N_NODES, D, (size_t)N_NODES * D);
        cudaEventRecord(evHtA, 0);
        gemm_mma_kernel<<<gHt4, 256, SM_BYTES>>>(h16, wrF_hi + 4 * 2048,
                                                 wrF_lo + 4 * 2048,
                                                 Ht + (size_t)4 * N_NODES * D, nullptr,
                                                 N_NODES, D, (size_t)N_NODES * D);
        cudaEventRecord(evHtB, 0);

        // s2: scatter chunk A after HtA, chunk B after HtB (ordered after init+gh)
        cudaStreamWaitEvent(s2, evHtA, 0);
        scatter_csr_kernel<<<csr_blocks, 256, 0, s2>>>(0);
        cudaStreamWaitEvent(s2, evHtB, 0);
        scatter_csr_kernel<<<csr_blocks, 256, 0, s2>>>(4);
        cudaEventRecord(evScat, s2);

        // main: fused gi GEMM + GRU gates (gh done before evScat by s2 ordering)
        cudaStreamWaitEvent(0, evScat, 0);
        gru_fused_kernel<<<mtiles32, 256, SMF_BYTES>>>(aggr, wihF_hi, wihF_lo,
                                                       gh, b_ih, h, N_NODES);
    }
}